// round 8
// baseline (speedup 1.0000x reference)
#include <cuda_runtime.h>
#include <cuda_bf16.h>
#include <cstdint>

// Problem constants (fixed by setup_inputs)
#define B_   8
#define NS   5
#define NQ   128
#define T_   16
#define D_   2048
#define NROWS (B_*NQ)           // 1024

#define GT   640
#define NCH  64                 // K chunks of 32 f32
#define PSTRIDE 257

// smem layout (bytes)
#define F32_STAGE 26624                       // 208 rows * 32 f32 * 4B
#define OFF_BF16  (4*F32_STAGE)               // 106496
#define BF_TILE   16640                       // 208 rows * 80B
#define OFF_SDIST (OFF_BF16 + 2*BF_TILE)      // 139776
#define OFF_SSP   (OFF_SDIST + 40*PSTRIDE*4)  // 180896 (1664 partials)
#define OFF_NORM  (OFF_SSP + 1664*4)          // 187552 (208 inv-norms)
#define OFF_T1    (OFF_NORM + 208*4)          // 188384
#define OFF_T2    (OFF_T1 + 40*4)
#define SMEM_BYTES (OFF_T2 + 40*4 + 32)       // ~188768

__device__ float g_rowterm[NROWS];
__device__ unsigned int g_done;   // zero-init; last block resets

#define LAM 0.1f
#define INVLAM 10.0f

__device__ __forceinline__ float softmin2(float a, float b) {
    float mn = fminf(a, b);
    return mn - LAM * __logf(1.0f + __expf(-fabsf(a - b) * INVLAM));
}
__device__ __forceinline__ float softmin3(float a, float b, float c) {
    float mn = fminf(fminf(a, b), c);
    float s = __expf((mn - a) * INVLAM) + __expf((mn - b) * INVLAM) + __expf((mn - c) * INVLAM);
    return mn - LAM * __logf(s);
}

__device__ __forceinline__ uint32_t smem_u32(const void* p) {
    uint32_t a;
    asm("{ .reg .u64 t; cvta.to.shared.u64 t, %1; cvt.u32.u64 %0, t; }" : "=r"(a) : "l"(p));
    return a;
}
__device__ __forceinline__ void ldsm4(uint32_t addr, uint32_t& r0, uint32_t& r1,
                                      uint32_t& r2, uint32_t& r3) {
    asm volatile("ldmatrix.sync.aligned.m8n8.x4.shared.b16 {%0,%1,%2,%3}, [%4];"
                 : "=r"(r0), "=r"(r1), "=r"(r2), "=r"(r3) : "r"(addr));
}
__device__ __forceinline__ void cpa16(uint32_t dst, const float* src) {
    asm volatile("cp.async.cg.shared.global [%0], [%1], 16;" :: "r"(dst), "l"(src));
}
// f32x4 -> packed bf16x4 (two u32)
__device__ __forceinline__ uint2 cvt_u2(float4 v) {
    union { __nv_bfloat162 h; uint32_t u; } lo, hi;
    lo.h = __floats2bfloat162_rn(v.x, v.y);
    hi.h = __floats2bfloat162_rn(v.z, v.w);
    return make_uint2(lo.u, hi.u);
}
#define DOT4(v) ((v).x*(v).x + (v).y*(v).y + (v).z*(v).z + (v).w*(v).w)

#define MMA(ac, a0,a1,a2,a3, b0, b1) \
    asm volatile( \
        "mma.sync.aligned.m16n8k16.row.col.f32.bf16.bf16.f32 " \
        "{%0,%1,%2,%3}, {%4,%5,%6,%7}, {%8,%9}, {%0,%1,%2,%3};\n" \
        : "+f"((ac)[0]), "+f"((ac)[1]), "+f"((ac)[2]), "+f"((ac)[3]) \
        : "r"(a0), "r"(a1), "r"(a2), "r"(a3), "r"(b0), "r"(b1))

// ---------------- fused kernel ----------------
// Block = (batch b, 128-query tile nt). Rows 0..79 = supp (M), 80..207 = query (N).
// cp.async stages raw f32 chunks (208 x 32 f32), convert pass makes bf16 tiles +
// accumulates per-segment sum-of-squares; 20 warps (5M x 4N) run mma.sync.
__global__ __launch_bounds__(GT, 1) void gemm_dtw_kernel(
        const float* __restrict__ supp, const float* __restrict__ query,
        const int* __restrict__ ys, float* __restrict__ out) {
    extern __shared__ char smc[];
    float* sDist = (float*)(smc + OFF_SDIST);
    float* ssp   = (float*)(smc + OFF_SSP);
    float* norm  = (float*)(smc + OFF_NORM);   // [0..79] supp inv, [80..207] query inv
    float* t1s   = (float*)(smc + OFF_T1);
    float* t2s   = (float*)(smc + OFF_T2);

    const int b = blockIdx.y, nt = blockIdx.x;
    const int tid = threadIdx.x, wid = tid >> 5, lane = tid & 31;
    const int wm = wid % 5;              // M warp tile (16 supp rows)
    const int wn = wid / 5;              // N warp tile (32 query cols)
    const int g = lane >> 2, t = lane & 3;
    const int quad = lane >> 3, qi = lane & 7;
    const uint32_t smb = smem_u32(smc);

    // ---- ldmatrix byte offsets within a bf16 tile ----
    const uint32_t offA  = (uint32_t)((wm*16 + qi + (quad & 1)*8) * 80 + (quad >> 1) * 16);
    const uint32_t offB0 = (uint32_t)((80 + wn*32      + (quad & 1)*8 + qi) * 80 + (quad >> 1) * 16);
    const uint32_t offB1 = (uint32_t)((80 + wn*32 + 16 + (quad & 1)*8 + qi) * 80 + (quad >> 1) * 16);

    // ---- per-thread segments: 16B of one row per chunk ----
    // seg s: row = s>>3 (0..207), f32 col base = (s&7)*4
    const int s0 = tid, s1 = tid + 640, s2 = tid + 1280;
    const bool has2 = (s2 < 1664);
    const int r0 = s0 >> 3, r1 = s1 >> 3, r2 = s2 >> 3;
    #define ROWPTR(r) ((r) < 80 ? supp + ((size_t)b*80 + (r))*D_ \
                               : query + ((size_t)(b*2048) + nt*128 + ((r)-80))*D_)
    const float* gp0 = ROWPTR(r0) + (s0 & 7)*4;
    const float* gp1 = ROWPTR(r1) + (s1 & 7)*4;
    const float* gp2 = ROWPTR(has2 ? r2 : 0) + (s2 & 7)*4;
    const uint32_t fo0 = (uint32_t)s0*16, fo1 = (uint32_t)s1*16, fo2 = (uint32_t)s2*16;
    const int bo0 = r0*80 + (s0 & 7)*8;
    const int bo1 = r1*80 + (s1 & 7)*8;
    const int bo2 = r2*80 + (s2 & 7)*8;

    float acc[4][4];
    #pragma unroll
    for (int j = 0; j < 4; j++) { acc[j][0]=0.f; acc[j][1]=0.f; acc[j][2]=0.f; acc[j][3]=0.f; }
    float ss0 = 0.f, ss1 = 0.f, ss2 = 0.f;

    // ---- prologue: stage chunks 0..2 ----
    #pragma unroll
    for (int c = 0; c < 3; c++) {
        const uint32_t sb = smb + (uint32_t)c * F32_STAGE;
        cpa16(sb + fo0, gp0 + c*32);
        cpa16(sb + fo1, gp1 + c*32);
        if (has2) cpa16(sb + fo2, gp2 + c*32);
        asm volatile("cp.async.commit_group;" ::: "memory");
    }

    // ---- mainloop: 64 chunks ----
    #pragma unroll 1
    for (int c = 0; c < NCH; c++) {
        const int nc = c + 3;
        if (nc < NCH) {
            const uint32_t sb = smb + (uint32_t)(nc & 3) * F32_STAGE;
            cpa16(sb + fo0, gp0 + nc*32);
            cpa16(sb + fo1, gp1 + nc*32);
            if (has2) cpa16(sb + fo2, gp2 + nc*32);
            asm volatile("cp.async.commit_group;" ::: "memory");
        }
        if      (c <  NCH-3) asm volatile("cp.async.wait_group 3;" ::: "memory");
        else if (c == NCH-3) asm volatile("cp.async.wait_group 2;" ::: "memory");
        else if (c == NCH-2) asm volatile("cp.async.wait_group 1;" ::: "memory");
        else                 asm volatile("cp.async.wait_group 0;" ::: "memory");
        __syncthreads();

        // ---- convert f32 stage (c&3) -> bf16 buf (c&1), accumulate sum-of-squares ----
        {
            const char* st = smc + (c & 3) * F32_STAGE;
            char* bt = smc + OFF_BF16 + (c & 1) * BF_TILE;
            float4 v0 = *(const float4*)(st + fo0);
            float4 v1 = *(const float4*)(st + fo1);
            ss0 += DOT4(v0); ss1 += DOT4(v1);
            *(uint2*)(bt + bo0) = cvt_u2(v0);
            *(uint2*)(bt + bo1) = cvt_u2(v1);
            if (has2) {
                float4 v2 = *(const float4*)(st + fo2);
                ss2 += DOT4(v2);
                *(uint2*)(bt + bo2) = cvt_u2(v2);
            }
        }
        __syncthreads();

        // ---- fragments + MMAs on bf16 buf (c&1) ----
        const uint32_t bufb = smb + OFF_BF16 + (uint32_t)(c & 1) * BF_TILE;
        #pragma unroll
        for (int ks = 0; ks < 2; ks++) {
            uint32_t a0, a1, a2, a3;
            ldsm4(bufb + offA + ks*32, a0, a1, a2, a3);
            uint32_t f0, f1, f2, f3, f4, f5, f6, f7;
            ldsm4(bufb + offB0 + ks*32, f0, f1, f2, f3);
            ldsm4(bufb + offB1 + ks*32, f4, f5, f6, f7);
            MMA(acc[0], a0,a1,a2,a3, f0, f2);
            MMA(acc[1], a0,a1,a2,a3, f1, f3);
            MMA(acc[2], a0,a1,a2,a3, f4, f6);
            MMA(acc[3], a0,a1,a2,a3, f5, f7);
        }
    }

    // ---- deterministic norm reduction ----
    ssp[s0] = ss0; ssp[s1] = ss1;
    if (has2) ssp[s2] = ss2;
    __syncthreads();
    if (tid < 208) {
        const float* sp = ssp + tid*8;
        float v = ((sp[0]+sp[1]) + (sp[2]+sp[3])) + ((sp[4]+sp[5]) + (sp[6]+sp[7]));
        norm[tid] = rsqrtf(fmaxf(v, 1e-12f));
    }
    __syncthreads();

    // ---- dist epilogue: acc -> sDist ----
    #pragma unroll
    for (int jj = 0; jj < 2; jj++) {
        #pragma unroll
        for (int p = 0; p < 2; p++) {
            const int idx = jj*2 + p;
            #pragma unroll
            for (int c4 = 0; c4 < 4; c4++) {
                const int lr = wm*16 + g + (c4 >> 1)*8;              // supp row 0..79
                const int qc = wn*32 + jj*16 + p*8 + t*2 + (c4 & 1); // query col 0..127
                const int s = lr >> 4, l = lr & 15;
                const int ql = qc >> 4, m = qc & 15;
                const float dval = 1.0f - acc[idx][c4] * norm[lr] * norm[80 + qc];
                sDist[(ql*NS + s) * PSTRIDE + (l << 4) + m] = dval;
            }
        }
    }
    __syncthreads();

    // ---- soft-DTW: 80 threads, one (problem, direction) each ----
    if (tid < 80) {
        const int pb = tid >> 1, dir = tid & 1;
        const float* dm = sDist + pb * PSTRIDE;
        const int base = dir ? 255 : 0;
        const int sgn = dir ? -1 : 1;

        float prev[T_ + 2];
        prev[0] = 0.f;
        #pragma unroll
        for (int m = 1; m <= T_; m++) prev[m] = prev[m - 1] + dm[base + sgn * (m - 1)];
        prev[T_ + 1] = prev[T_];

        for (int l = 1; l < T_; l++) {
            const int rb = base + sgn * (l * 16);
            float drow[T_];
            #pragma unroll
            for (int m = 0; m < T_; m++) drow[m] = dm[rb + sgn * m];
            float left = 0.f;
            float dprev = prev[0];
            #pragma unroll
            for (int m = 1; m <= T_ + 1; m++) {
                const float up = prev[m];
                const float d = (m <= T_) ? drow[m - 1] : 0.f;
                float val;
                if (m == 1 || m == T_ + 1) val = softmin3(dprev, left, up) + d;
                else                        val = softmin2(dprev, left) + d;
                dprev = up;
                prev[m] = val;
                left = val;
            }
        }
        if (dir == 0) t1s[pb] = prev[T_ + 1];
        else          t2s[pb] = prev[T_ + 1];
    }
    __syncthreads();

    // ---- per-block outputs: tam + per-query CE term ----
    if (tid < 40) {
        const int qloc = tid / NS, s = tid % NS;
        const int row = b * NQ + nt * 8 + qloc;
        out[1 + row * NS + s] = 0.5f * (t1s[tid] + t2s[tid]);
    }
    if (tid < 8) {
        const int row = b * NQ + nt * 8 + tid;
        float t1[NS], t2[NS];
        #pragma unroll
        for (int s = 0; s < NS; s++) { t1[s] = t1s[tid * NS + s]; t2[s] = t2s[tid * NS + s]; }
        float mx1 = -t1[0], mx2 = -t2[0];
        #pragma unroll
        for (int s = 1; s < NS; s++) { mx1 = fmaxf(mx1, -t1[s]); mx2 = fmaxf(mx2, -t2[s]); }
        float se1 = 0.f, se2 = 0.f;
        #pragma unroll
        for (int s = 0; s < NS; s++) { se1 += __expf(-t1[s] - mx1); se2 += __expf(-t2[s] - mx2); }
        const int y = ys[row];
        g_rowterm[row] = (mx1 + __logf(se1) + t1[y]) + (mx2 + __logf(se2) + t2[y]);
    }

    // ---- last block computes the final loss ----
    __shared__ unsigned s_last;
    __shared__ float s_red[20];
    __threadfence();
    __syncthreads();
    if (tid == 0) s_last = (atomicAdd(&g_done, 1u) == 127u) ? 1u : 0u;
    __syncthreads();
    if (s_last) {
        float v = 0.f;
        if (tid < 512) v = g_rowterm[tid] + g_rowterm[tid + 512];
        #pragma unroll
        for (int o = 16; o; o >>= 1) v += __shfl_xor_sync(0xffffffffu, v, o);
        if (lane == 0 && wid < 16) s_red[wid] = v;
        __syncthreads();
        if (wid == 0) {
            float u = (lane < 16) ? s_red[lane] : 0.f;
            #pragma unroll
            for (int o = 8; o; o >>= 1) u += __shfl_xor_sync(0xffffffffu, u, o);
            if (lane == 0) { out[0] = 0.5f * u / (float)NROWS; g_done = 0u; }
        }
    }
}

// ---------------- launch ----------------
extern "C" void kernel_launch(void* const* d_in, const int* in_sizes, int n_in,
                              void* d_out, int out_size) {
    const float* supp  = (const float*)d_in[0];
    const float* query = (const float*)d_in[1];
    const int*   ys    = (const int*)d_in[2];
    float* out = (float*)d_out;

    static bool attr_set = false;
    if (!attr_set) {
        cudaFuncSetAttribute(gemm_dtw_kernel,
                             cudaFuncAttributeMaxDynamicSharedMemorySize, SMEM_BYTES);
        attr_set = true;
    }

    gemm_dtw_kernel<<<dim3(16, B_), GT, SMEM_BYTES>>>(supp, query, ys, out);
}